// round 15
// baseline (speedup 1.0000x reference)
#include <cuda_runtime.h>
#include <cuda_fp16.h>
#include <cstdint>
#include <math.h>

#define BATCH   32
#define TOK     197
#define NPATCH  196
#define DIM     768
#define HEADS   12
#define DH      64
#define QKVDIM  2304
#define FF      3072
#define DEPTH   12
#define MROWS   (BATCH*TOK)
#define MPATCH  (BATCH*NPATCH)
#define MPAD    6400
#define NMAT    46

// ternary weights TRANSPOSED [N,K] row-major as half {-1,0,+1}; fp weights as half
__device__ __half g_wqkv[DEPTH*QKVDIM*DIM];
__device__ __half g_wo  [DEPTH*DIM*DIM];
__device__ __half g_w1  [11*FF*DIM];
__device__ __half g_w2  [11*DIM*FF];
__device__ __half g_wfpT[DIM*DIM + FF*DIM + DIM*FF];
__device__ float  g_x   [MPAD*DIM];
__device__ float  g_h   [MPAD*DIM];
__device__ float  g_o   [MPAD*DIM];
__device__ float  g_p4  [4*MPAD*DIM];   // split-K partials for W2
__device__ __half g_qkvh[MPAD*QKVDIM];
__device__ __half g_hh  [MPAD*DIM];
__device__ __half g_oh  [MPAD*DIM];
__device__ __half g_mlph[MPAD*FF];

__device__ unsigned int       g_hist2[NMAT][256];
__device__ double             g_part2[NMAT][64];
__device__ unsigned int       g_prefix2[NMAT];
__device__ unsigned long long g_rank2[NMAT];
__device__ unsigned long long g_cntle2[NMAT];
__device__ unsigned int       g_mingt2[NMAT];
__device__ float              g_thr2[NMAT];
__device__ float              g_scale2[NMAT];

// ---------------- helpers ----------------
__device__ __forceinline__ uint32_t smem_u32(const void* p) {
    uint32_t a;
    asm("{ .reg .u64 t; cvta.to.shared.u64 t, %1; cvt.u32.u64 %0, t; }" : "=r"(a) : "l"(p));
    return a;
}
__device__ __forceinline__ void cp_async16(uint32_t dst, const void* src) {
    asm volatile("cp.async.cg.shared.global [%0], [%1], 16;" :: "r"(dst), "l"(src));
}
#define CP_COMMIT() asm volatile("cp.async.commit_group;" ::: "memory")
#define CP_WAIT(n)  asm volatile("cp.async.wait_group %0;" :: "n"(n) : "memory")

#define MMA_F16(d, a, b) \
    asm volatile("mma.sync.aligned.m16n8k16.row.col.f32.f16.f16.f32 " \
        "{%0,%1,%2,%3}, {%4,%5,%6,%7}, {%8,%9}, {%0,%1,%2,%3};" \
        : "+f"((d)[0]), "+f"((d)[1]), "+f"((d)[2]), "+f"((d)[3]) \
        : "r"((a)[0]), "r"((a)[1]), "r"((a)[2]), "r"((a)[3]), "r"((b)[0]), "r"((b)[1]))

#define LDSM_X4(r0, r1, r2, r3, addr) \
    asm volatile("ldmatrix.sync.aligned.m8n8.x4.shared.b16 {%0,%1,%2,%3}, [%4];" \
        : "=r"(r0), "=r"(r1), "=r"(r2), "=r"(r3) : "r"(addr))

__device__ __forceinline__ void store2(float* C, long long ob, float x0, float x1) {
    *reinterpret_cast<float2*>(C + ob) = make_float2(x0, x1);
}
__device__ __forceinline__ void store2(__half* C, long long ob, float x0, float x1) {
    *reinterpret_cast<__half2*>(C + ob) = __floats2half2_rn(x0, x1);
}

// ---------------- batched ternary quantization ----------------
__device__ __forceinline__ void mat_meta(int m, const float* Wqkv, const float* Wo,
                                         const float* W1, const float* W2,
                                         const float** src, int* n) {
    if (m < 12)      { *src = Wqkv + (long long)m * DIM * QKVDIM;      *n = DIM * QKVDIM; }
    else if (m < 24) { *src = Wo   + (long long)(m - 12) * DIM * DIM;  *n = DIM * DIM; }
    else if (m < 35) { *src = W1   + (long long)(m - 24) * DIM * FF;   *n = DIM * FF; }
    else             { *src = W2   + (long long)(m - 35) * FF * DIM;   *n = FF * DIM; }
}
__device__ __forceinline__ int mat_n(int m) {
    return (m < 12) ? DIM * QKVDIM : (m < 24) ? DIM * DIM : DIM * FF;
}

__global__ void q_init() {
    int m = blockIdx.x;
    g_hist2[m][threadIdx.x] = 0u;
    if (threadIdx.x == 0) {
        g_prefix2[m] = 0u;
        g_rank2[m] = (unsigned long long)(mat_n(m) / 2 - 1);
    }
}

__global__ void __launch_bounds__(256) q_hist(const float* __restrict__ Wqkv, const float* __restrict__ Wo,
                                              const float* __restrict__ W1, const float* __restrict__ W2, int shift) {
    int m = blockIdx.y;
    const float* src; int n;
    mat_meta(m, Wqkv, Wo, W1, W2, &src, &n);
    __shared__ unsigned int h[256];
    __shared__ double red[256];
    h[threadIdx.x] = 0u;
    __syncthreads();
    unsigned mask = (shift == 24) ? 0u : (0xFFFFFFFFu << (shift + 8));
    unsigned pref = g_prefix2[m] & mask;
    float ls = 0.f;
    for (int i = blockIdx.x * 256 + threadIdx.x; i < n; i += 64 * 256) {
        unsigned bits = __float_as_uint(src[i]) & 0x7FFFFFFFu;
        if (shift == 24) ls += __uint_as_float(bits);
        if ((bits & mask) == pref) atomicAdd(&h[(bits >> shift) & 0xFFu], 1u);
    }
    __syncthreads();
    atomicAdd(&g_hist2[m][threadIdx.x], h[threadIdx.x]);
    if (shift == 24) {
        red[threadIdx.x] = (double)ls;
        __syncthreads();
        for (int s = 128; s > 0; s >>= 1) {
            if (threadIdx.x < s) red[threadIdx.x] += red[threadIdx.x + s];
            __syncthreads();
        }
        if (threadIdx.x == 0) g_part2[m][blockIdx.x] = red[0];
    }
}

__global__ void q_scan(int shift) {
    int m = threadIdx.x;
    if (m >= NMAT) return;
    if (shift == 24) {
        double s = 0.0;
        for (int i = 0; i < 64; i++) s += g_part2[m][i];
        g_scale2[m] = (float)(s / (double)mat_n(m));
    }
    unsigned long long r = g_rank2[m], cum = 0ull, cumBefore = 0ull;
    int bin = -1;
    for (int i = 0; i < 256; i++) {
        unsigned c = g_hist2[m][i];
        g_hist2[m][i] = 0u;
        if (bin < 0) {
            if (cum + c > r) { bin = i; cumBefore = cum; }
            else cum += c;
        }
    }
    if (bin < 0) bin = 255;
    g_prefix2[m] |= ((unsigned)bin) << shift;
    g_rank2[m] = r - cumBefore;
    if (shift == 0) { g_cntle2[m] = 0ull; g_mingt2[m] = 0x7FFFFFFFu; }
}

__global__ void __launch_bounds__(256) q_pass2(const float* __restrict__ Wqkv, const float* __restrict__ Wo,
                                               const float* __restrict__ W1, const float* __restrict__ W2) {
    int m = blockIdx.y;
    const float* src; int n;
    mat_meta(m, Wqkv, Wo, W1, W2, &src, &n);
    __shared__ unsigned long long cr[256];
    __shared__ unsigned int mr[256];
    unsigned v1 = g_prefix2[m];
    unsigned long long lc = 0ull;
    unsigned lm = 0x7FFFFFFFu;
    for (int i = blockIdx.x * 256 + threadIdx.x; i < n; i += 64 * 256) {
        unsigned bits = __float_as_uint(src[i]) & 0x7FFFFFFFu;
        if (bits <= v1) lc++;
        else lm = min(lm, bits);
    }
    cr[threadIdx.x] = lc; mr[threadIdx.x] = lm;
    __syncthreads();
    for (int s = 128; s > 0; s >>= 1) {
        if (threadIdx.x < s) {
            cr[threadIdx.x] += cr[threadIdx.x + s];
            mr[threadIdx.x] = min(mr[threadIdx.x], mr[threadIdx.x + s]);
        }
        __syncthreads();
    }
    if (threadIdx.x == 0) {
        atomicAdd(&g_cntle2[m], cr[0]);
        atomicMin(&g_mingt2[m], mr[0]);
    }
}

__global__ void q_fin() {
    int m = threadIdx.x;
    if (m >= NMAT) return;
    unsigned long long k0 = (unsigned long long)(mat_n(m) / 2 - 1);
    float v1 = __uint_as_float(g_prefix2[m]);
    float v2 = (g_cntle2[m] >= k0 + 2ull) ? v1 : __uint_as_float(g_mingt2[m]);
    g_thr2[m] = 0.5f * v1 + 0.5f * v2;
}

__global__ void __launch_bounds__(256) q_quantT(const float* __restrict__ Wqkv, const float* __restrict__ Wo,
                                                const float* __restrict__ W1, const float* __restrict__ W2,
                                                __half* __restrict__ wq, __half* __restrict__ wo,
                                                __half* __restrict__ w1, __half* __restrict__ w2) {
    int m = blockIdx.z;
    int K, N; const float* src; __half* dst;
    if (m < 12)      { K = DIM; N = QKVDIM; src = Wqkv + (long long)m * DIM * QKVDIM;      dst = wq + (long long)m * QKVDIM * DIM; }
    else if (m < 24) { K = DIM; N = DIM;    src = Wo   + (long long)(m - 12) * DIM * DIM;  dst = wo + (long long)(m - 12) * DIM * DIM; }
    else if (m < 35) { K = DIM; N = FF;     src = W1   + (long long)(m - 24) * DIM * FF;   dst = w1 + (long long)(m - 24) * FF * DIM; }
    else             { K = FF;  N = DIM;    src = W2   + (long long)(m - 35) * FF * DIM;   dst = w2 + (long long)(m - 35) * DIM * FF; }
    int n0 = blockIdx.x * 32, k0 = blockIdx.y * 32;
    if (n0 >= N || k0 >= K) return;
    __shared__ float t[32][33];
    float thr = g_thr2[m];
    #pragma unroll
    for (int j = 0; j < 4; j++)
        t[threadIdx.y + j * 8][threadIdx.x] =
            src[(long long)(k0 + threadIdx.y + j * 8) * N + n0 + threadIdx.x];
    __syncthreads();
    #pragma unroll
    for (int j = 0; j < 4; j++) {
        float v = t[threadIdx.x][threadIdx.y + j * 8];
        float q = (fabsf(v) >= thr) ? ((v > 0.f) ? 1.f : ((v < 0.f) ? -1.f : 0.f)) : 0.f;
        dst[(long long)(n0 + threadIdx.y + j * 8) * K + k0 + threadIdx.x] = __float2half_rn(q);
    }
}

__global__ void __launch_bounds__(256) fpT_k(const float* __restrict__ Wp, const float* __restrict__ W1,
                                             const float* __restrict__ W2, __half* __restrict__ dstBase) {
    int z = blockIdx.z;
    int K, N; const float* src; __half* dst;
    if (z == 0)      { K = DIM; N = DIM; src = Wp;                            dst = dstBase; }
    else if (z == 1) { K = DIM; N = FF;  src = W1 + (long long)11 * DIM * FF; dst = dstBase + DIM * DIM; }
    else             { K = FF;  N = DIM; src = W2 + (long long)11 * FF * DIM; dst = dstBase + DIM * DIM + FF * DIM; }
    int n0 = blockIdx.x * 32, k0 = blockIdx.y * 32;
    if (n0 >= N || k0 >= K) return;
    __shared__ float t[32][33];
    #pragma unroll
    for (int j = 0; j < 4; j++)
        t[threadIdx.y + j * 8][threadIdx.x] =
            src[(long long)(k0 + threadIdx.y + j * 8) * N + n0 + threadIdx.x];
    __syncthreads();
    #pragma unroll
    for (int j = 0; j < 4; j++)
        dst[(long long)(n0 + threadIdx.y + j * 8) * K + k0 + threadIdx.x] =
            __float2half_rn(t[threadIdx.x][threadIdx.y + j * 8]);
}

// ---------------- patchify / assemble ----------------
__global__ void patchify_k(const float* __restrict__ img, float* __restrict__ out) {
    int idx = blockIdx.x * 256 + threadIdx.x;
    if (idx >= MPATCH * DIM) return;
    int d = idx % DIM;
    int t = (idx / DIM) % NPATCH;
    int b = idx / (DIM * NPATCH);
    int c = d % 3, p = d / 3;
    int p1 = p >> 4, p2 = p & 15;
    int hh = t / 14, ww = t % 14;
    out[idx] = img[(((long long)b * 3 + c) * 224 + (hh * 16 + p1)) * 224 + (ww * 16 + p2)];
}

__global__ void assemble_k(const float* __restrict__ emb, const float* __restrict__ cls,
                           const float* __restrict__ pos, float* __restrict__ x) {
    int idx = blockIdx.x * 256 + threadIdx.x;
    if (idx >= MROWS * DIM) return;
    int d = idx % DIM;
    int t = (idx / DIM) % TOK;
    int b = idx / (DIM * TOK);
    float v;
    if (t == 0) v = cls[d] + pos[d];
    else        v = emb[((long long)b * NPATCH + (t - 1)) * DIM + d] + pos[(long long)t * DIM + d];
    x[idx] = v;
}

// ---------------- split-K reduce: X += P0+P1+P2+P3 + bias ----------------
__global__ void __launch_bounds__(256) red4_k(const float* __restrict__ P, const float* __restrict__ bias,
                                              float* __restrict__ X) {
    int idx = blockIdx.x * 256 + threadIdx.x;
    if (idx >= MROWS * DIM) return;
    int col = idx % DIM;
    X[idx] += P[idx] + P[idx + MPAD*DIM] + P[idx + 2*MPAD*DIM] + P[idx + 3*MPAD*DIM] + bias[col];
}

// ---------------- layernorm ----------------
__global__ void __launch_bounds__(256) ln_k(const float* __restrict__ in, const float* __restrict__ gam,
                                            const float* __restrict__ bet, float* __restrict__ out) {
    __shared__ float red[256];
    long long row = blockIdx.x;
    const float* x = in + row * DIM;
    int tid = threadIdx.x;
    float v0 = x[tid], v1 = x[tid + 256], v2 = x[tid + 512];
    red[tid] = v0 + v1 + v2;
    __syncthreads();
    for (int s = 128; s > 0; s >>= 1) {
        if (tid < s) red[tid] += red[tid + s];
        __syncthreads();
    }
    float mean = red[0] * (1.f / 768.f);
    __syncthreads();
    float d0 = v0 - mean, d1 = v1 - mean, d2 = v2 - mean;
    red[tid] = d0 * d0 + d1 * d1 + d2 * d2;
    __syncthreads();
    for (int s = 128; s > 0; s >>= 1) {
        if (tid < s) red[tid] += red[tid + s];
        __syncthreads();
    }
    float inv = rsqrtf(red[0] * (1.f / 768.f) + 1e-5f);
    float* o = out + row * DIM;
    o[tid]       = d0 * inv * gam[tid]       + bet[tid];
    o[tid + 256] = d1 * inv * gam[tid + 256] + bet[tid + 256];
    o[tid + 512] = d2 * inv * gam[tid + 512] + bet[tid + 512];
}

__global__ void __launch_bounds__(256) ln_h(const float* __restrict__ in, const float* __restrict__ gam,
                                            const float* __restrict__ bet, __half* __restrict__ out) {
    __shared__ float red[256];
    long long row = blockIdx.x;
    const float* x = in + row * DIM;
    int tid = threadIdx.x;
    float v0 = x[tid], v1 = x[tid + 256], v2 = x[tid + 512];
    red[tid] = v0 + v1 + v2;
    __syncthreads();
    for (int s = 128; s > 0; s >>= 1) {
        if (tid < s) red[tid] += red[tid + s];
        __syncthreads();
    }
    float mean = red[0] * (1.f / 768.f);
    __syncthreads();
    float d0 = v0 - mean, d1 = v1 - mean, d2 = v2 - mean;
    red[tid] = d0 * d0 + d1 * d1 + d2 * d2;
    __syncthreads();
    for (int s = 128; s > 0; s >>= 1) {
        if (tid < s) red[tid] += red[tid + s];
        __syncthreads();
    }
    float inv = rsqrtf(red[0] * (1.f / 768.f) + 1e-5f);
    __half* o = out + row * DIM;
    o[tid]       = __float2half_rn(d0 * inv * gam[tid]       + bet[tid]);
    o[tid + 256] = __float2half_rn(d1 * inv * gam[tid + 256] + bet[tid + 256]);
    o[tid + 512] = __float2half_rn(d2 * inv * gam[tid + 512] + bet[tid + 512]);
}

// ---------------- fp16 mma.sync GEMM (ldmatrix, 2 CTAs/SM, 128x128) ----------------
// MODE_PART: split-K over gridDim.z=4; each z writes alpha*acc to its partial slab.
#define MODE_STORE 0
#define MODE_RESID 1
#define MODE_GELU  2
#define MODE_PART  3
#define GH_A     10240
#define GH_STAGE 20480
#define GH_SMEM  (4 * GH_STAGE)   // 81920 -> 2 CTAs/SM

template<int MODE, typename TOUT>
__global__ void __launch_bounds__(256, 2) gemm_h(const __half* __restrict__ A,
                                                 const __half* __restrict__ Bt,
                                                 const float* __restrict__ bias,
                                                 const float* __restrict__ R,
                                                 const float* __restrict__ alphaPtr,
                                                 TOUT* __restrict__ C,
                                                 int N, int K) {
    extern __shared__ char smh[];
    uint32_t sbase = smem_u32(smh);
    int tid = threadIdx.x, lane = tid & 31, wid = tid >> 5;
    int wm = wid & 1, wn = wid >> 1;
    int row0 = blockIdx.y * 128, col0 = blockIdx.x * 128;

    const int Kl   = (MODE == MODE_PART) ? (K >> 2) : K;
    const int zoff = (MODE == MODE_PART) ? blockIdx.z * Kl : 0;
    const long long pout = (MODE == MODE_PART) ? (long long)blockIdx.z * MPAD * DIM : 0;
    const int KT   = Kl >> 5;

    float acc[4][4][4];
    #pragma unroll
    for (int i = 0; i < 4; i++)
        #pragma unroll
        for (int j = 0; j < 4; j++)
            #pragma unroll
            for (int v = 0; v < 4; v++) acc[i][j][v] = 0.f;

    int ar = tid >> 1, ac = (tid & 1) * 2;

    auto load_stage = [&](int buf, int kt) {
        int k0 = (kt << 5) + zoff;
        const __half* gA = A + (long long)(row0 + ar) * K + k0;
        uint32_t sA = sbase + (uint32_t)buf * GH_STAGE + (uint32_t)ar * 80u;
        cp_async16(sA + (uint32_t)(ac * 16),       gA + ac * 8);
        cp_async16(sA + (uint32_t)((ac + 1) * 16), gA + (ac + 1) * 8);
        const __half* gB = Bt + (long long)(col0 + ar) * K + k0;
        uint32_t sB = sbase + (uint32_t)buf * GH_STAGE + GH_A + (uint32_t)ar * 80u;
        cp_async16(sB + (uint32_t)(ac * 16),       gB + ac * 8);
        cp_async16(sB + (uint32_t)((ac + 1) * 16), gB + (ac + 1) * 8);
        CP_COMMIT();
    };

    load_stage(0, 0);
    if (KT > 1) load_stage(1, 1);
    if (KT > 2) load_stage(2, 2);

    uint32_t aAddr[4], bAddr[2];
    {
        int la = lane & 15, lau = lane >> 4;
        #pragma unroll
        for (int mt = 0; mt < 4; mt++)
            aAddr[mt] = sbase + (uint32_t)((wm * 64 + mt * 16 + la) * 80 + lau * 16);
        int lb = (lane & 7) + ((lane >> 4) << 3), lbu = (lane >> 3) & 1;
        #pragma unroll
        for (int np = 0; np < 2; np++)
            bAddr[np] = sbase + GH_A + (uint32_t)((wn * 32 + np * 16 + lb) * 80 + lbu * 16);
    }

    for (int kt = 0; kt < KT; kt++) {
        if (kt + 2 < KT)      { CP_WAIT(2); }
        else if (kt + 1 < KT) { CP_WAIT(1); }
        else                  { CP_WAIT(0); }
        __syncthreads();
        if (kt + 3 < KT) load_stage((kt + 3) & 3, kt + 3);

        uint32_t so = (uint32_t)((kt & 3) * GH_STAGE);
        #pragma unroll
        for (int ks = 0; ks < 2; ks++) {
            uint32_t kb = so + ks * 32;
            uint32_t b[2][4];
            #pragma unroll
            for (int np = 0; np < 2; np++)
                LDSM_X4(b[np][0], b[np][1], b[np][2], b[np][3], bAddr[np] + kb);
            #pragma unroll
            for (int mt = 0; mt < 4; mt++) {
                uint32_t a[4];
                LDSM_X4(a[0], a[1], a[2], a[3], aAddr[mt] + kb);
                #pragma unroll
                for (int np = 0; np < 2; np++) {
                    MMA_F16(acc[mt][np * 2],     a, (&b[np][0]));
                    MMA_F16(acc[mt][np * 2 + 1], a, (&b[np][2]));
                }
            }
        }
    }

    float alpha = alphaPtr ? alphaPtr[0] : 1.0f;
    int fr = lane >> 2;
    int c2 = (lane & 3) * 2;
    #pragma unroll
    for (int mt = 0; mt < 4; mt++) {
        #pragma unroll
        for (int nt = 0; nt < 4; nt++) {
            int row = row0 + wm * 64 + mt * 16 + fr;
            int col = col0 + wn * 32 + nt * 8 + c2;
            #pragma unroll
            for (int hh = 0; hh < 2; hh++) {
                long long ob = (long long)(row + hh * 8) * N + col;
                float x0 = acc[mt][nt][hh * 2 + 0] * alpha;
                float x1 = acc[mt][nt][hh * 2 + 1] * alpha;
                if (MODE == MODE_PART) {
                    store2((float*)C + pout, ob, x0, x1);
                } else {
                    x0 += bias[col]; x1 += bias[col + 1];
                    if (MODE == MODE_RESID) {
                        float2 rr = *reinterpret_cast<const float2*>(R + ob);
                        x0 += rr.x; x1 += rr.y;
                    }
                    if (MODE == MODE_GELU) {
                        #define G1(t) (0.5f * (t) * (1.f + tanhf(0.7978845608028654f * ((t) + 0.044715f * (t) * (t) * (t)))))
                        x0 = G1(x0); x1 = G1(x1);
                        #undef G1
                    }
                    store2(C, ob, x0, x1);
                }
            }
        }
    }
}

// ---------------- attention (half2 smem, fp32 accumulation) ----------------
#define KV2_STRIDE 33
#define KV2_ROW    (TOK * KV2_STRIDE)
#define ATTN_SMEM_BYTES (2 * KV2_ROW * 4 + 8 * 32 * 4 + 8 * 200 * 4)

__global__ void __launch_bounds__(256) attn_k(const __half* __restrict__ qkv, __half* __restrict__ o) {
    extern __shared__ char smc[];
    __half2* ks2 = (__half2*)smc;
    __half2* vs2 = ks2 + KV2_ROW;
    __half2* qs2 = vs2 + KV2_ROW;
    float*   ps  = (float*)(qs2 + 8 * 32);

    int h = blockIdx.x, b = blockIdx.y;
    int tid = threadIdx.x, lane = tid & 31, w = tid >> 5;
    const long long rowbase = (long long)b * TOK * QKVDIM;
    const int hoff = h * DH;

    for (int idx = tid; idx < TOK * 32; idx += 256) {
        int j = idx >> 5, dp = idx & 31;
        const __half* base = qkv + rowbase + (long long)j * QKVDIM + hoff + dp * 2;
        ks2[j * KV2_STRIDE + dp] = *reinterpret_cast<const __half2*>(base + DIM);
        vs2[j * KV2_STRIDE + dp] = *reinterpret_cast<const __half2*>(base + 2 * DIM);
    }
    __syncthreads();

    for (int i = w; i < TOK; i += 8) {
        qs2[w * 32 + lane] = *reinterpret_cast<const __half2*>(
            qkv + rowbase + (long long)i * QKVDIM + hoff + lane * 2);
        __syncwarp();

        float s[7];
        #pragma unroll
        for (int t = 0; t < 7; t++) {
            int j = lane + 32 * t;
            float a = -1e30f;
            if (j < TOK) {
                a = 0.f;
                const __half2* kr = ks2 + j * KV2_STRIDE;
                const __half2* qr = qs2 + w * 32;
                #pragma unroll
                for (int dp = 0; dp < 32; dp++) {
                    float2 kf = __half22float2(kr[dp]);
                    float2 qf = __half22float2(qr[dp]);
                    a += qf.x * kf.x + qf.y * kf.y;
                }
                a *= 0.125f;
            }
            s[t] = a;
        }
        float m = s[0];
        #pragma unroll
        for (int t = 1; t < 7; t++) m = fmaxf(m, s[t]);
        #pragma unroll
        for (int off = 16; off; off >>= 1) m = fmaxf(m, __shfl_xor_sync(0xffffffffu, m, off));
        float sum = 0.f;
        #pragma unroll
        for (int t = 0; t < 7; t++) { s[t] = expf(s[t] - m); sum += s[t]; }
        #pragma unroll
        for (int off = 16; off; off >>= 1) sum += __shfl_xor_sync(0xffffffffu, sum, off);
        float inv = 1.f / sum;
        #pragma unroll
        for (int t = 0; t < 7; t++) {
            int j = lane + 32 * t;
            if (j < TOK) ps[w * 200 + j] = s[t] * inv;
        }
        __syncwarp();

        float a0 = 0.f, a1 = 0.f;
        for (int j = 0; j < TOK; j++) {
            float pj = ps[w * 200 + j];
            float2 vf = __half22float2(vs2[j * KV2_STRIDE + lane]);
            a0 += pj * vf.x;
            a1 += pj * vf.y;
        }
        long long obase = ((long long)b * TOK + i) * DIM + hoff + lane * 2;
        *reinterpret_cast<__half2*>(o + obase) = __floats2half2_rn(a0, a1);
        __syncwarp();
    }
}

// ---------------- host ----------------
extern "C" void kernel_launch(void* const* d_in, const int* in_sizes, int n_in,
                              void* d_out, int out_size) {
    const float* img        = (const float*)d_in[0];
    const float* patch_ln_g = (const float*)d_in[1];
    const float* patch_ln_b = (const float*)d_in[2];
    const float* W_patch    = (const float*)d_in[3];
    const float* b_patch    = (const float*)d_in[4];
    const float* emb_ln_g   = (const float*)d_in[5];
    const float* emb_ln_b   = (const float*)d_in[6];
    const float* pos_emb    = (const float*)d_in[7];
    const float* cls_token  = (const float*)d_in[8];
    const float* ln1_g      = (const float*)d_in[9];
    const float* ln1_b      = (const float*)d_in[10];
    const float* Wqkv       = (const float*)d_in[11];
    const float* b_qkv      = (const float*)d_in[12];
    const float* Wo         = (const float*)d_in[13];
    const float* b_o        = (const float*)d_in[14];
    const float* ln2_g      = (const float*)d_in[15];
    const float* ln2_b      = (const float*)d_in[16];
    const float* W1         = (const float*)d_in[17];
    const float* b1         = (const float*)d_in[18];
    const float* W2         = (const float*)d_in[19];
    const float* b2         = (const float*)d_in[20];
    const float* norm_g     = (const float*)d_in[21];
    const float* norm_b     = (const float*)d_in[22];

    __half *wq, *wo, *w1q, *w2q, *wfpT, *Hh, *Oh, *MLPh, *QKVh;
    float *X, *H, *O, *SC, *P4;
    cudaGetSymbolAddress((void**)&wq,   g_wqkv);
    cudaGetSymbolAddress((void**)&wo,   g_wo);
    cudaGetSymbolAddress((void**)&w1q,  g_w1);
    cudaGetSymbolAddress((void**)&w2q,  g_w2);
    cudaGetSymbolAddress((void**)&wfpT, g_wfpT);
    cudaGetSymbolAddress((void**)&X,    g_x);
    cudaGetSymbolAddress((void**)&H,    g_h);
    cudaGetSymbolAddress((void**)&O,    g_o);
    cudaGetSymbolAddress((void**)&P4,   g_p4);
    cudaGetSymbolAddress((void**)&QKVh, g_qkvh);
    cudaGetSymbolAddress((void**)&Hh,   g_hh);
    cudaGetSymbolAddress((void**)&Oh,   g_oh);
    cudaGetSymbolAddress((void**)&MLPh, g_mlph);
    cudaGetSymbolAddress((void**)&SC,   g_scale2);

    cudaFuncSetAttribute(attn_k, cudaFuncAttributeMaxDynamicSharedMemorySize, ATTN_SMEM_BYTES);
    cudaFuncSetAttribute(gemm_h<MODE_STORE, float>,  cudaFuncAttributeMaxDynamicSharedMemorySize, GH_SMEM);
    cudaFuncSetAttribute(gemm_h<MODE_STORE, __half>, cudaFuncAttributeMaxDynamicSharedMemorySize, GH_SMEM);
    cudaFuncSetAttribute(gemm_h<MODE_RESID, float>,  cudaFuncAttributeMaxDynamicSharedMemorySize, GH_SMEM);
    cudaFuncSetAttribute(gemm_h<MODE_GELU,  __half>, cudaFuncAttributeMaxDynamicSharedMemorySize, GH_SMEM);
    cudaFuncSetAttribute(gemm_h<MODE_PART,  float>,  cudaFuncAttributeMaxDynamicSharedMemorySize, GH_SMEM);

    // prologue (patch gemm early for ncu window)
    patchify_k<<<(MPATCH * DIM + 255) / 256, 256>>>(img, H);                 // 0
    ln_h<<<MPATCH, 256>>>(H, patch_ln_g, patch_ln_b, Hh);                    // 1
    fpT_k<<<dim3(96, 96, 3), dim3(32, 8)>>>(W_patch, W1, W2, wfpT);          // 2
    gemm_h<MODE_STORE, float><<<dim3(DIM / 128, MPATCH / 128), 256, GH_SMEM>>>(
        Hh, wfpT, b_patch, nullptr, nullptr, O, DIM, DIM);                   // 3 <- profile target
    q_init<<<NMAT, 256>>>();
    for (int rr = 0; rr < 4; rr++) {
        int shift = 24 - 8 * rr;
        q_hist<<<dim3(64, NMAT), 256>>>(Wqkv, Wo, W1, W2, shift);
        q_scan<<<1, 64>>>(shift);
    }
    q_pass2<<<dim3(64, NMAT), 256>>>(Wqkv, Wo, W1, W2);
    q_fin<<<1, 64>>>();
    q_quantT<<<dim3(96, 96, NMAT), dim3(32, 8)>>>(Wqkv, Wo, W1, W2, wq, wo, w1q, w2q);

    ln_k<<<MPATCH, 256>>>(O, emb_ln_g, emb_ln_b, H);
    assemble_k<<<(MROWS * DIM + 255) / 256, 256>>>(H, cls_token, pos_emb, X);

    const __half* W1T11 = wfpT + DIM * DIM;
    const __half* W2T11 = wfpT + DIM * DIM + FF * DIM;

    dim3 gQKV (QKVDIM / 128, MPAD / 128);
    dim3 gDIM (DIM / 128,    MPAD / 128);
    dim3 gDIM4(DIM / 128,    MPAD / 128, 4);   // split-K=4 for W2
    dim3 gFF  (FF / 128,     MPAD / 128);

    for (int i = 0; i < DEPTH; i++) {
        ln_h<<<MROWS, 256>>>(X, ln1_g + i * DIM, ln1_b + i * DIM, Hh);
        gemm_h<MODE_STORE, __half><<<gQKV, 256, GH_SMEM>>>(
            Hh, wq + (long long)i * QKVDIM * DIM, b_qkv + i * QKVDIM, nullptr, SC + i, QKVh, QKVDIM, DIM);
        attn_k<<<dim3(HEADS, BATCH), 256, ATTN_SMEM_BYTES>>>(QKVh, Oh);
        gemm_h<MODE_RESID, float><<<gDIM, 256, GH_SMEM>>>(
            Oh, wo + (long long)i * DIM * DIM, b_o + i * DIM, X, SC + 12 + i, X, DIM, DIM);
        ln_h<<<MROWS, 256>>>(X, ln2_g + i * DIM, ln2_b + i * DIM, Hh);
        const __half* w1p = (i < DEPTH - 1) ? (w1q + (long long)i * FF * DIM) : W1T11;
        const __half* w2p = (i < DEPTH - 1) ? (w2q + (long long)i * DIM * FF) : W2T11;
        const float* a1p = (i < DEPTH - 1) ? (SC + 24 + i) : nullptr;
        const float* a2p = (i < DEPTH - 1) ? (SC + 35 + i) : nullptr;
        gemm_h<MODE_GELU, __half><<<gFF, 256, GH_SMEM>>>(
            Hh, w1p, b1 + i * FF, nullptr, a1p, MLPh, FF, DIM);
        gemm_h<MODE_PART, float><<<gDIM4, 256, GH_SMEM>>>(
            MLPh, w2p, nullptr, nullptr, a2p, P4, DIM, FF);
        red4_k<<<(MROWS * DIM + 255) / 256, 256>>>(P4, b2 + i * DIM, X);
    }

    ln_k<<<MROWS, 256>>>(X, norm_g, norm_b, (float*)d_out);
}

// round 16
// speedup vs baseline: 1.0627x; 1.0627x over previous
#include <cuda_runtime.h>
#include <cuda_fp16.h>
#include <cstdint>
#include <math.h>

#define BATCH   32
#define TOK     197
#define NPATCH  196
#define DIM     768
#define HEADS   12
#define DH      64
#define QKVDIM  2304
#define FF      3072
#define DEPTH   12
#define MROWS   (BATCH*TOK)
#define MPATCH  (BATCH*NPATCH)
#define MPAD    6400
#define NMAT    46

// ternary weights TRANSPOSED [N,K] row-major as half {-1,0,+1}; fp weights as half
__device__ __half g_wqkv[DEPTH*QKVDIM*DIM];
__device__ __half g_wo  [DEPTH*DIM*DIM];
__device__ __half g_w1  [11*FF*DIM];
__device__ __half g_w2  [11*DIM*FF];
__device__ __half g_wfpT[DIM*DIM + FF*DIM + DIM*FF];
__device__ float  g_x   [MPAD*DIM];
__device__ float  g_h   [MPAD*DIM];
__device__ float  g_o   [MPAD*DIM];
__device__ __half g_qkvh[MPAD*QKVDIM];
__device__ __half g_hh  [MPAD*DIM];
__device__ __half g_oh  [MPAD*DIM];
__device__ __half g_mlph[MPAD*FF];

__device__ unsigned int       g_hist2[NMAT][256];
__device__ double             g_part2[NMAT][64];
__device__ unsigned int       g_prefix2[NMAT];
__device__ unsigned long long g_rank2[NMAT];
__device__ unsigned long long g_cntle2[NMAT];
__device__ unsigned int       g_mingt2[NMAT];
__device__ float              g_thr2[NMAT];
__device__ float              g_scale2[NMAT];

// ---------------- helpers ----------------
__device__ __forceinline__ uint32_t smem_u32(const void* p) {
    uint32_t a;
    asm("{ .reg .u64 t; cvta.to.shared.u64 t, %1; cvt.u32.u64 %0, t; }" : "=r"(a) : "l"(p));
    return a;
}
__device__ __forceinline__ void cp_async16(uint32_t dst, const void* src) {
    asm volatile("cp.async.cg.shared.global [%0], [%1], 16;" :: "r"(dst), "l"(src));
}
#define CP_COMMIT() asm volatile("cp.async.commit_group;" ::: "memory")
#define CP_WAIT(n)  asm volatile("cp.async.wait_group %0;" :: "n"(n) : "memory")

#define MMA_F16(d, a, b) \
    asm volatile("mma.sync.aligned.m16n8k16.row.col.f32.f16.f16.f32 " \
        "{%0,%1,%2,%3}, {%4,%5,%6,%7}, {%8,%9}, {%0,%1,%2,%3};" \
        : "+f"((d)[0]), "+f"((d)[1]), "+f"((d)[2]), "+f"((d)[3]) \
        : "r"((a)[0]), "r"((a)[1]), "r"((a)[2]), "r"((a)[3]), "r"((b)[0]), "r"((b)[1]))

#define LDSM_X4(r0, r1, r2, r3, addr) \
    asm volatile("ldmatrix.sync.aligned.m8n8.x4.shared.b16 {%0,%1,%2,%3}, [%4];" \
        : "=r"(r0), "=r"(r1), "=r"(r2), "=r"(r3) : "r"(addr))

__device__ __forceinline__ void store2(float* C, long long ob, float x0, float x1) {
    *reinterpret_cast<float2*>(C + ob) = make_float2(x0, x1);
}
__device__ __forceinline__ void store2(__half* C, long long ob, float x0, float x1) {
    *reinterpret_cast<__half2*>(C + ob) = __floats2half2_rn(x0, x1);
}
__device__ __forceinline__ void stor1(float* o, int i, float v)  { o[i] = v; }
__device__ __forceinline__ void stor1(__half* o, int i, float v) { o[i] = __float2half_rn(v); }

// ---------------- batched ternary quantization ----------------
__device__ __forceinline__ void mat_meta(int m, const float* Wqkv, const float* Wo,
                                         const float* W1, const float* W2,
                                         const float** src, int* n) {
    if (m < 12)      { *src = Wqkv + (long long)m * DIM * QKVDIM;      *n = DIM * QKVDIM; }
    else if (m < 24) { *src = Wo   + (long long)(m - 12) * DIM * DIM;  *n = DIM * DIM; }
    else if (m < 35) { *src = W1   + (long long)(m - 24) * DIM * FF;   *n = DIM * FF; }
    else             { *src = W2   + (long long)(m - 35) * FF * DIM;   *n = FF * DIM; }
}
__device__ __forceinline__ int mat_n(int m) {
    return (m < 12) ? DIM * QKVDIM : (m < 24) ? DIM * DIM : DIM * FF;
}

__global__ void q_init() {
    int m = blockIdx.x;
    g_hist2[m][threadIdx.x] = 0u;
    if (threadIdx.x == 0) {
        g_prefix2[m] = 0u;
        g_rank2[m] = (unsigned long long)(mat_n(m) / 2 - 1);
    }
}

__global__ void __launch_bounds__(256) q_hist(const float* __restrict__ Wqkv, const float* __restrict__ Wo,
                                              const float* __restrict__ W1, const float* __restrict__ W2, int shift) {
    int m = blockIdx.y;
    const float* src; int n;
    mat_meta(m, Wqkv, Wo, W1, W2, &src, &n);
    __shared__ unsigned int h[256];
    __shared__ double red[256];
    h[threadIdx.x] = 0u;
    __syncthreads();
    unsigned mask = (shift == 24) ? 0u : (0xFFFFFFFFu << (shift + 8));
    unsigned pref = g_prefix2[m] & mask;
    float ls = 0.f;
    for (int i = blockIdx.x * 256 + threadIdx.x; i < n; i += 64 * 256) {
        unsigned bits = __float_as_uint(src[i]) & 0x7FFFFFFFu;
        if (shift == 24) ls += __uint_as_float(bits);
        if ((bits & mask) == pref) atomicAdd(&h[(bits >> shift) & 0xFFu], 1u);
    }
    __syncthreads();
    atomicAdd(&g_hist2[m][threadIdx.x], h[threadIdx.x]);
    if (shift == 24) {
        red[threadIdx.x] = (double)ls;
        __syncthreads();
        for (int s = 128; s > 0; s >>= 1) {
            if (threadIdx.x < s) red[threadIdx.x] += red[threadIdx.x + s];
            __syncthreads();
        }
        if (threadIdx.x == 0) g_part2[m][blockIdx.x] = red[0];
    }
}

__global__ void q_scan(int shift) {
    int m = threadIdx.x;
    if (m >= NMAT) return;
    if (shift == 24) {
        double s = 0.0;
        for (int i = 0; i < 64; i++) s += g_part2[m][i];
        g_scale2[m] = (float)(s / (double)mat_n(m));
    }
    unsigned long long r = g_rank2[m], cum = 0ull, cumBefore = 0ull;
    int bin = -1;
    for (int i = 0; i < 256; i++) {
        unsigned c = g_hist2[m][i];
        g_hist2[m][i] = 0u;
        if (bin < 0) {
            if (cum + c > r) { bin = i; cumBefore = cum; }
            else cum += c;
        }
    }
    if (bin < 0) bin = 255;
    g_prefix2[m] |= ((unsigned)bin) << shift;
    g_rank2[m] = r - cumBefore;
    if (shift == 0) { g_cntle2[m] = 0ull; g_mingt2[m] = 0x7FFFFFFFu; }
}

__global__ void __launch_bounds__(256) q_pass2(const float* __restrict__ Wqkv, const float* __restrict__ Wo,
                                               const float* __restrict__ W1, const float* __restrict__ W2) {
    int m = blockIdx.y;
    const float* src; int n;
    mat_meta(m, Wqkv, Wo, W1, W2, &src, &n);
    __shared__ unsigned long long cr[256];
    __shared__ unsigned int mr[256];
    unsigned v1 = g_prefix2[m];
    unsigned long long lc = 0ull;
    unsigned lm = 0x7FFFFFFFu;
    for (int i = blockIdx.x * 256 + threadIdx.x; i < n; i += 64 * 256) {
        unsigned bits = __float_as_uint(src[i]) & 0x7FFFFFFFu;
        if (bits <= v1) lc++;
        else lm = min(lm, bits);
    }
    cr[threadIdx.x] = lc; mr[threadIdx.x] = lm;
    __syncthreads();
    for (int s = 128; s > 0; s >>= 1) {
        if (threadIdx.x < s) {
            cr[threadIdx.x] += cr[threadIdx.x + s];
            mr[threadIdx.x] = min(mr[threadIdx.x], mr[threadIdx.x + s]);
        }
        __syncthreads();
    }
    if (threadIdx.x == 0) {
        atomicAdd(&g_cntle2[m], cr[0]);
        atomicMin(&g_mingt2[m], mr[0]);
    }
}

__global__ void q_fin() {
    int m = threadIdx.x;
    if (m >= NMAT) return;
    unsigned long long k0 = (unsigned long long)(mat_n(m) / 2 - 1);
    float v1 = __uint_as_float(g_prefix2[m]);
    float v2 = (g_cntle2[m] >= k0 + 2ull) ? v1 : __uint_as_float(g_mingt2[m]);
    g_thr2[m] = 0.5f * v1 + 0.5f * v2;
}

__global__ void __launch_bounds__(256) q_quantT(const float* __restrict__ Wqkv, const float* __restrict__ Wo,
                                                const float* __restrict__ W1, const float* __restrict__ W2,
                                                __half* __restrict__ wq, __half* __restrict__ wo,
                                                __half* __restrict__ w1, __half* __restrict__ w2) {
    int m = blockIdx.z;
    int K, N; const float* src; __half* dst;
    if (m < 12)      { K = DIM; N = QKVDIM; src = Wqkv + (long long)m * DIM * QKVDIM;      dst = wq + (long long)m * QKVDIM * DIM; }
    else if (m < 24) { K = DIM; N = DIM;    src = Wo   + (long long)(m - 12) * DIM * DIM;  dst = wo + (long long)(m - 12) * DIM * DIM; }
    else if (m < 35) { K = DIM; N = FF;     src = W1   + (long long)(m - 24) * DIM * FF;   dst = w1 + (long long)(m - 24) * FF * DIM; }
    else             { K = FF;  N = DIM;    src = W2   + (long long)(m - 35) * FF * DIM;   dst = w2 + (long long)(m - 35) * DIM * FF; }
    int n0 = blockIdx.x * 32, k0 = blockIdx.y * 32;
    if (n0 >= N || k0 >= K) return;
    __shared__ float t[32][33];
    float thr = g_thr2[m];
    #pragma unroll
    for (int j = 0; j < 4; j++)
        t[threadIdx.y + j * 8][threadIdx.x] =
            src[(long long)(k0 + threadIdx.y + j * 8) * N + n0 + threadIdx.x];
    __syncthreads();
    #pragma unroll
    for (int j = 0; j < 4; j++) {
        float v = t[threadIdx.x][threadIdx.y + j * 8];
        float q = (fabsf(v) >= thr) ? ((v > 0.f) ? 1.f : ((v < 0.f) ? -1.f : 0.f)) : 0.f;
        dst[(long long)(n0 + threadIdx.y + j * 8) * K + k0 + threadIdx.x] = __float2half_rn(q);
    }
}

__global__ void __launch_bounds__(256) fpT_k(const float* __restrict__ Wp, const float* __restrict__ W1,
                                             const float* __restrict__ W2, __half* __restrict__ dstBase) {
    int z = blockIdx.z;
    int K, N; const float* src; __half* dst;
    if (z == 0)      { K = DIM; N = DIM; src = Wp;                            dst = dstBase; }
    else if (z == 1) { K = DIM; N = FF;  src = W1 + (long long)11 * DIM * FF; dst = dstBase + DIM * DIM; }
    else             { K = FF;  N = DIM; src = W2 + (long long)11 * FF * DIM; dst = dstBase + DIM * DIM + FF * DIM; }
    int n0 = blockIdx.x * 32, k0 = blockIdx.y * 32;
    if (n0 >= N || k0 >= K) return;
    __shared__ float t[32][33];
    #pragma unroll
    for (int j = 0; j < 4; j++)
        t[threadIdx.y + j * 8][threadIdx.x] =
            src[(long long)(k0 + threadIdx.y + j * 8) * N + n0 + threadIdx.x];
    __syncthreads();
    #pragma unroll
    for (int j = 0; j < 4; j++)
        dst[(long long)(n0 + threadIdx.y + j * 8) * K + k0 + threadIdx.x] =
            __float2half_rn(t[threadIdx.x][threadIdx.y + j * 8]);
}

// ---------------- patchify / assemble ----------------
__global__ void patchify_k(const float* __restrict__ img, float* __restrict__ out) {
    int idx = blockIdx.x * 256 + threadIdx.x;
    if (idx >= MPATCH * DIM) return;
    int d = idx % DIM;
    int t = (idx / DIM) % NPATCH;
    int b = idx / (DIM * NPATCH);
    int c = d % 3, p = d / 3;
    int p1 = p >> 4, p2 = p & 15;
    int hh = t / 14, ww = t % 14;
    out[idx] = img[(((long long)b * 3 + c) * 224 + (hh * 16 + p1)) * 224 + (ww * 16 + p2)];
}

__global__ void assemble_k(const float* __restrict__ emb, const float* __restrict__ cls,
                           const float* __restrict__ pos, float* __restrict__ x) {
    int idx = blockIdx.x * 256 + threadIdx.x;
    if (idx >= MROWS * DIM) return;
    int d = idx % DIM;
    int t = (idx / DIM) % TOK;
    int b = idx / (DIM * TOK);
    float v;
    if (t == 0) v = cls[d] + pos[d];
    else        v = emb[((long long)b * NPATCH + (t - 1)) * DIM + d] + pos[(long long)t * DIM + d];
    x[idx] = v;
}

// ---------------- layernorm: warp per row, shuffle reductions ----------------
template<typename TOUT>
__global__ void __launch_bounds__(256) ln_w(const float* __restrict__ in, const float* __restrict__ gam,
                                            const float* __restrict__ bet, TOUT* __restrict__ out,
                                            int nrows) {
    int w = threadIdx.x >> 5, lane = threadIdx.x & 31;
    long long row = (long long)blockIdx.x * 8 + w;
    if (row >= nrows) return;
    const float* x = in + row * DIM;
    float v[24];
    float s = 0.f;
    #pragma unroll
    for (int i = 0; i < 24; i++) { v[i] = x[lane + 32 * i]; s += v[i]; }
    #pragma unroll
    for (int off = 16; off; off >>= 1) s += __shfl_xor_sync(0xffffffffu, s, off);
    float mean = s * (1.f / 768.f);
    float q = 0.f;
    #pragma unroll
    for (int i = 0; i < 24; i++) { float d = v[i] - mean; q += d * d; }
    #pragma unroll
    for (int off = 16; off; off >>= 1) q += __shfl_xor_sync(0xffffffffu, q, off);
    float inv = rsqrtf(q * (1.f / 768.f) + 1e-5f);
    TOUT* o = out + row * DIM;
    #pragma unroll
    for (int i = 0; i < 24; i++) {
        int c = lane + 32 * i;
        stor1(o, c, (v[i] - mean) * inv * gam[c] + bet[c]);
    }
}

// ---------------- fp16 mma.sync GEMM (ldmatrix, 2 CTAs/SM, 128x128) ----------------
#define MODE_STORE 0
#define MODE_RESID 1
#define MODE_GELU  2
#define GH_A     10240
#define GH_STAGE 20480
#define GH_SMEM  (4 * GH_STAGE)   // 81920 -> 2 CTAs/SM

template<int MODE, typename TOUT>
__global__ void __launch_bounds__(256, 2) gemm_h(const __half* __restrict__ A,
                                                 const __half* __restrict__ Bt,
                                                 const float* __restrict__ bias,
                                                 const float* __restrict__ R,
                                                 const float* __restrict__ alphaPtr,
                                                 TOUT* __restrict__ C,
                                                 int N, int K) {
    extern __shared__ char smh[];
    uint32_t sbase = smem_u32(smh);
    int tid = threadIdx.x, lane = tid & 31, wid = tid >> 5;
    int wm = wid & 1, wn = wid >> 1;
    int row0 = blockIdx.y * 128, col0 = blockIdx.x * 128;

    float acc[4][4][4];
    #pragma unroll
    for (int i = 0; i < 4; i++)
        #pragma unroll
        for (int j = 0; j < 4; j++)
            #pragma unroll
            for (int v = 0; v < 4; v++) acc[i][j][v] = 0.f;

    const int KT = K >> 5;
    int ar = tid >> 1, ac = (tid & 1) * 2;

    auto load_stage = [&](int buf, int kt) {
        int k0 = kt << 5;
        const __half* gA = A + (long long)(row0 + ar) * K + k0;
        uint32_t sA = sbase + (uint32_t)buf * GH_STAGE + (uint32_t)ar * 80u;
        cp_async16(sA + (uint32_t)(ac * 16),       gA + ac * 8);
        cp_async16(sA + (uint32_t)((ac + 1) * 16), gA + (ac + 1) * 8);
        const __half* gB = Bt + (long long)(col0 + ar) * K + k0;
        uint32_t sB = sbase + (uint32_t)buf * GH_STAGE + GH_A + (uint32_t)ar * 80u;
        cp_async16(sB + (uint32_t)(ac * 16),       gB + ac * 8);
        cp_async16(sB + (uint32_t)((ac + 1) * 16), gB + (ac + 1) * 8);
        CP_COMMIT();
    };

    load_stage(0, 0);
    load_stage(1, 1);
    load_stage(2, 2);

    uint32_t aAddr[4], bAddr[2];
    {
        int la = lane & 15, lau = lane >> 4;
        #pragma unroll
        for (int mt = 0; mt < 4; mt++)
            aAddr[mt] = sbase + (uint32_t)((wm * 64 + mt * 16 + la) * 80 + lau * 16);
        int lb = (lane & 7) + ((lane >> 4) << 3), lbu = (lane >> 3) & 1;
        #pragma unroll
        for (int np = 0; np < 2; np++)
            bAddr[np] = sbase + GH_A + (uint32_t)((wn * 32 + np * 16 + lb) * 80 + lbu * 16);
    }

    for (int kt = 0; kt < KT; kt++) {
        if (kt + 2 < KT)      { CP_WAIT(2); }
        else if (kt + 1 < KT) { CP_WAIT(1); }
        else                  { CP_WAIT(0); }
        __syncthreads();
        if (kt + 3 < KT) load_stage((kt + 3) & 3, kt + 3);

        uint32_t so = (uint32_t)((kt & 3) * GH_STAGE);
        #pragma unroll
        for (int ks = 0; ks < 2; ks++) {
            uint32_t kb = so + ks * 32;
            uint32_t b[2][4];
            #pragma unroll
            for (int np = 0; np < 2; np++)
                LDSM_X4(b[np][0], b[np][1], b[np][2], b[np][3], bAddr[np] + kb);
            #pragma unroll
            for (int mt = 0; mt < 4; mt++) {
                uint32_t a[4];
                LDSM_X4(a[0], a[1], a[2], a[3], aAddr[mt] + kb);
                #pragma unroll
                for (int np = 0; np < 2; np++) {
                    MMA_F16(acc[mt][np * 2],     a, (&b[np][0]));
                    MMA_F16(acc[mt][np * 2 + 1], a, (&b[np][2]));
                }
            }
        }
    }

    float alpha = alphaPtr ? alphaPtr[0] : 1.0f;
    int fr = lane >> 2;
    int c2 = (lane & 3) * 2;
    #pragma unroll
    for (int mt = 0; mt < 4; mt++) {
        #pragma unroll
        for (int nt = 0; nt < 4; nt++) {
            int row = row0 + wm * 64 + mt * 16 + fr;
            int col = col0 + wn * 32 + nt * 8 + c2;
            float b0v = bias[col], b1v = bias[col + 1];
            #pragma unroll
            for (int hh = 0; hh < 2; hh++) {
                long long ob = (long long)(row + hh * 8) * N + col;
                float x0 = acc[mt][nt][hh * 2 + 0] * alpha + b0v;
                float x1 = acc[mt][nt][hh * 2 + 1] * alpha + b1v;
                if (MODE == MODE_RESID) {
                    float2 rr = *reinterpret_cast<const float2*>(R + ob);
                    x0 += rr.x; x1 += rr.y;
                }
                if (MODE == MODE_GELU) {
                    #define G1(t) (0.5f * (t) * (1.f + tanhf(0.7978845608028654f * ((t) + 0.044715f * (t) * (t) * (t)))))
                    x0 = G1(x0); x1 = G1(x1);
                    #undef G1
                }
                store2(C, ob, x0, x1);
            }
        }
    }
}

// ---------------- attention (half2 smem, fp32 accumulation) ----------------
#define KV2_STRIDE 33
#define KV2_ROW    (TOK * KV2_STRIDE)
#define ATTN_SMEM_BYTES (2 * KV2_ROW * 4 + 8 * 32 * 4 + 8 * 200 * 4)

__global__ void __launch_bounds__(256) attn_k(const __half* __restrict__ qkv, __half* __restrict__ o) {
    extern __shared__ char smc[];
    __half2* ks2 = (__half2*)smc;
    __half2* vs2 = ks2 + KV2_ROW;
    __half2* qs2 = vs2 + KV2_ROW;
    float*   ps  = (float*)(qs2 + 8 * 32);

    int h = blockIdx.x, b = blockIdx.y;
    int tid = threadIdx.x, lane = tid & 31, w = tid >> 5;
    const long long rowbase = (long long)b * TOK * QKVDIM;
    const int hoff = h * DH;

    for (int idx = tid; idx < TOK * 32; idx += 256) {
        int j = idx >> 5, dp = idx & 31;
        const __half* base = qkv + rowbase + (long long)j * QKVDIM + hoff + dp * 2;
        ks2[j * KV2_STRIDE + dp] = *reinterpret_cast<const __half2*>(base + DIM);
        vs2[j * KV2_STRIDE + dp] = *reinterpret_cast<const __half2*>(base + 2 * DIM);
    }
    __syncthreads();

    for (int i = w; i < TOK; i += 8) {
        qs2[w * 32 + lane] = *reinterpret_cast<const __half2*>(
            qkv + rowbase + (long long)i * QKVDIM + hoff + lane * 2);
        __syncwarp();

        float s[7];
        #pragma unroll
        for (int t = 0; t < 7; t++) {
            int j = lane + 32 * t;
            float a = -1e30f;
            if (j < TOK) {
                a = 0.f;
                const __half2* kr = ks2 + j * KV2_STRIDE;
                const __half2* qr = qs2 + w * 32;
                #pragma unroll
                for (int dp = 0; dp < 32; dp++) {
                    float2 kf = __half22float2(kr[dp]);
                    float2 qf = __half22float2(qr[dp]);
                    a += qf.x * kf.x + qf.y * kf.y;
                }
                a *= 0.125f;
            }
            s[t] = a;
        }
        float m = s[0];
        #pragma unroll
        for (int t = 1; t < 7; t++) m = fmaxf(m, s[t]);
        #pragma unroll
        for (int off = 16; off; off >>= 1) m = fmaxf(m, __shfl_xor_sync(0xffffffffu, m, off));
        float sum = 0.f;
        #pragma unroll
        for (int t = 0; t < 7; t++) { s[t] = expf(s[t] - m); sum += s[t]; }
        #pragma unroll
        for (int off = 16; off; off >>= 1) sum += __shfl_xor_sync(0xffffffffu, sum, off);
        float inv = 1.f / sum;
        #pragma unroll
        for (int t = 0; t < 7; t++) {
            int j = lane + 32 * t;
            if (j < TOK) ps[w * 200 + j] = s[t] * inv;
        }
        __syncwarp();

        float a0 = 0.f, a1 = 0.f;
        for (int j = 0; j < TOK; j++) {
            float pj = ps[w * 200 + j];
            float2 vf = __half22float2(vs2[j * KV2_STRIDE + lane]);
            a0 += pj * vf.x;
            a1 += pj * vf.y;
        }
        long long obase = ((long long)b * TOK + i) * DIM + hoff + lane * 2;
        *reinterpret_cast<__half2*>(o + obase) = __floats2half2_rn(a0, a1);
        __syncwarp();
    }
}

// ---------------- host ----------------
extern "C" void kernel_launch(void* const* d_in, const int* in_sizes, int n_in,
                              void* d_out, int out_size) {
    const float* img        = (const float*)d_in[0];
    const float* patch_ln_g = (const float*)d_in[1];
    const float* patch_ln_b = (const float*)d_in[2];
    const float* W_patch    = (const float*)d_in[3];
    const float* b_patch    = (const float*)d_in[4];
    const float* emb_ln_g   = (const float*)d_in[5];
    const float* emb_ln_b   = (const float*)d_in[6];
    const float* pos_emb    = (const float*)d_in[7];
    const float* cls_token  = (const float*)d_in[8];
    const float* ln1_g      = (const float*)d_in[9];
    const float* ln1_b      = (const float*)d_in[10];
    const float* Wqkv       = (const float*)d_in[11];
    const float* b_qkv      = (const float*)d_in[12];
    const float* Wo         = (const float*)d_in[13];
    const float* b_o        = (const float*)d_in[14];
    const float* ln2_g      = (const float*)d_in[15];
    const float* ln2_b      = (const float*)d_in[16];
    const float* W1         = (const float*)d_in[17];
    const float* b1         = (const float*)d_in[18];
    const float* W2         = (const float*)d_in[19];
    const float* b2         = (const float*)d_in[20];
    const float* norm_g     = (const float*)d_in[21];
    const float* norm_b     = (const float*)d_in[22];

    __half *wq, *wo, *w1q, *w2q, *wfpT, *Hh, *Oh, *MLPh, *QKVh;
    float *X, *H, *O, *SC;
    cudaGetSymbolAddress((void**)&wq,   g_wqkv);
    cudaGetSymbolAddress((void**)&wo,   g_wo);
    cudaGetSymbolAddress((void**)&w1q,  g_w1);
    cudaGetSymbolAddress((void**)&w2q,  g_w2);
    cudaGetSymbolAddress((void**)&wfpT, g_wfpT);
    cudaGetSymbolAddress((void**)&X,    g_x);
    cudaGetSymbolAddress((void**)&H,    g_h);
    cudaGetSymbolAddress((void**)&O,    g_o);
    cudaGetSymbolAddress((void**)&QKVh, g_qkvh);
    cudaGetSymbolAddress((void**)&Hh,   g_hh);
    cudaGetSymbolAddress((void**)&Oh,   g_oh);
    cudaGetSymbolAddress((void**)&MLPh, g_mlph);
    cudaGetSymbolAddress((void**)&SC,   g_scale2);

    cudaFuncSetAttribute(attn_k, cudaFuncAttributeMaxDynamicSharedMemorySize, ATTN_SMEM_BYTES);
    cudaFuncSetAttribute(gemm_h<MODE_STORE, float>,  cudaFuncAttributeMaxDynamicSharedMemorySize, GH_SMEM);
    cudaFuncSetAttribute(gemm_h<MODE_STORE, __half>, cudaFuncAttributeMaxDynamicSharedMemorySize, GH_SMEM);
    cudaFuncSetAttribute(gemm_h<MODE_RESID, float>,  cudaFuncAttributeMaxDynamicSharedMemorySize, GH_SMEM);
    cudaFuncSetAttribute(gemm_h<MODE_GELU,  __half>, cudaFuncAttributeMaxDynamicSharedMemorySize, GH_SMEM);

    // prologue (patch gemm early for ncu window)
    patchify_k<<<(MPATCH * DIM + 255) / 256, 256>>>(img, H);                 // 0
    ln_w<__half><<<MPATCH / 8, 256>>>(H, patch_ln_g, patch_ln_b, Hh, MPATCH);// 1
    fpT_k<<<dim3(96, 96, 3), dim3(32, 8)>>>(W_patch, W1, W2, wfpT);          // 2
    gemm_h<MODE_STORE, float><<<dim3(DIM / 128, MPATCH / 128), 256, GH_SMEM>>>(
        Hh, wfpT, b_patch, nullptr, nullptr, O, DIM, DIM);                   // 3 <- profile target
    q_init<<<NMAT, 256>>>();
    for (int rr = 0; rr < 4; rr++) {
        int shift = 24 - 8 * rr;
        q_hist<<<dim3(64, NMAT), 256>>>(Wqkv, Wo, W1, W2, shift);
        q_scan<<<1, 64>>>(shift);
    }
    q_pass2<<<dim3(64, NMAT), 256>>>(Wqkv, Wo, W1, W2);
    q_fin<<<1, 64>>>();
    q_quantT<<<dim3(96, 96, NMAT), dim3(32, 8)>>>(Wqkv, Wo, W1, W2, wq, wo, w1q, w2q);

    ln_w<float><<<MPATCH / 8, 256>>>(O, emb_ln_g, emb_ln_b, H, MPATCH);
    assemble_k<<<(MROWS * DIM + 255) / 256, 256>>>(H, cls_token, pos_emb, X);

    const __half* W1T11 = wfpT + DIM * DIM;
    const __half* W2T11 = wfpT + DIM * DIM + FF * DIM;

    dim3 gQKV(QKVDIM / 128, MPAD / 128);
    dim3 gDIM(DIM / 128,    MPAD / 128);
    dim3 gFF (FF / 128,     MPAD / 128);
    int lnGrid = MROWS / 8;   // 6304 / 8 = 788

    for (int i = 0; i < DEPTH; i++) {
        ln_w<__half><<<lnGrid, 256>>>(X, ln1_g + i * DIM, ln1_b + i * DIM, Hh, MROWS);
        gemm_h<MODE_STORE, __half><<<gQKV, 256, GH_SMEM>>>(
            Hh, wq + (long long)i * QKVDIM * DIM, b_qkv + i * QKVDIM, nullptr, SC + i, QKVh, QKVDIM, DIM);
        attn_k<<<dim3(HEADS, BATCH), 256, ATTN_SMEM_BYTES>>>(QKVh, Oh);
        gemm_h<MODE_RESID, float><<<gDIM, 256, GH_SMEM>>>(
            Oh, wo + (long long)i * DIM * DIM, b_o + i * DIM, X, SC + 12 + i, X, DIM, DIM);
        ln_w<__half><<<lnGrid, 256>>>(X, ln2_g + i * DIM, ln2_b + i * DIM, Hh, MROWS);
        const __half* w1p = (i < DEPTH - 1) ? (w1q + (long long)i * FF * DIM) : W1T11;
        const __half* w2p = (i < DEPTH - 1) ? (w2q + (long long)i * DIM * FF) : W2T11;
        const float* a1p = (i < DEPTH - 1) ? (SC + 24 + i) : nullptr;
        const float* a2p = (i < DEPTH - 1) ? (SC + 35 + i) : nullptr;
        gemm_h<MODE_GELU, __half><<<gFF, 256, GH_SMEM>>>(
            Hh, w1p, b1 + i * FF, nullptr, a1p, MLPh, FF, DIM);
        gemm_h<MODE_RESID, float><<<gDIM, 256, GH_SMEM>>>(
            MLPh, w2p, b2 + i * DIM, X, a2p, X, DIM, FF);
    }

    ln_w<float><<<lnGrid, 256>>>(X, norm_g, norm_b, (float*)d_out, MROWS);
}